// round 17
// baseline (speedup 1.0000x reference)
#include <cuda_runtime.h>

#define NB 8
#define PP 2304
#define QTOT (NB*PP)       // 18432
#define CIN 64
#define OUTC 384
#define NSTRIDE (OUTC*PP)
#define SLICE (64*PP)
#define NS 9               // split-K factor for visual attention
#define COLW 56            // (qkv0 only) smem row width

// Scratch (allocation-free rule: __device__ globals)
__device__ float g_q[NB*8*PP];
__device__ float g_k[NB*8*PP];
__device__ float g_v[NB*32*PP];
__device__ float g_pl[NS*QTOT];
__device__ float g_pv[NS*32*QTOT];   // [split][c][q] — warp-coalesced
__device__ float g_x[QTOT*64];       // [p][n][c] mega-kernel input
__device__ float g_wt[5*4096];       // per head: [64][48] qkv-T (3072) + [32][32] conv-T (1024)

typedef unsigned long long u64;

__device__ __forceinline__ u64 fma2(u64 a,u64 b,u64 c){u64 d;asm("fma.rn.f32x2 %0,%1,%2,%3;":"=l"(d):"l"(a),"l"(b),"l"(c));return d;}
__device__ __forceinline__ u64 add2(u64 a,u64 b){u64 d;asm("add.rn.f32x2 %0,%1,%2;":"=l"(d):"l"(a),"l"(b));return d;}
__device__ __forceinline__ u64 pack2(float lo,float hi){u64 d;asm("mov.b64 %0,{%1,%2};":"=l"(d):"f"(lo),"f"(hi));return d;}
__device__ __forceinline__ void unpack2(u64 v,float&lo,float&hi){asm("mov.b64 {%0,%1},%2;":"=f"(lo),"=f"(hi):"l"(v));}
__device__ __forceinline__ float ex2f(float x){float y;asm("ex2.approx.ftz.f32 %0,%1;":"=f"(y):"f"(x));return y;}

__device__ __forceinline__ float dot4(float4 a, float4 b){
    return a.x*b.x + a.y*b.y + a.z*b.z + a.w*b.w;
}

// ---------------------------------------------------------------------------
// One-shot weight transpose: [o][c] (gmem) -> [c][o] flat per head in g_wt.
// ---------------------------------------------------------------------------
__global__ __launch_bounds__(256) void transpose_w(
    const float* __restrict__ tq_w, const float* __restrict__ tk_w,
    const float* __restrict__ tv_w, const float* __restrict__ tc_w)
{
    int i = blockIdx.x*256 + threadIdx.x;
    if (i >= 5*4096) return;
    int h = i >> 12, r = i & 4095;
    float v;
    if (r < 3072) {
        int c = r / 48, o = r % 48;
        v = (o<8)  ? tq_w[h*512  + o*64 + c]
          : (o<16) ? tk_w[h*512  + (o-8)*64 + c]
                   : tv_w[h*2048 + (o-16)*64 + c];
    } else {
        int rr = r - 3072;
        int c = rr >> 5, o = rr & 31;
        v = tc_w[h*1024 + o*32 + c];
    }
    g_wt[i] = v;
}

// ---------------------------------------------------------------------------
// Stage-0 QKV, 4-way split (unchanged).
// ---------------------------------------------------------------------------
__global__ __launch_bounds__(128) void qkv0_kernel(
    const float* __restrict__ src,
    const float* __restrict__ qw, const float* __restrict__ qb,
    const float* __restrict__ kw, const float* __restrict__ kb,
    const float* __restrict__ vw, const float* __restrict__ vb)
{
    __shared__ alignas(16) float swt[64*52];
    __shared__ alignas(16) float sbs[48];
    __shared__ alignas(16) float xsm[64*COLW];

    const int tid = threadIdx.x;
    const int wq = tid >> 5, l = tid & 31;
    const int pos = l & 3, n = l >> 2;
    const int col = 8 + pos*12 + n;
    const int pg = blockIdx.x*4;

    for (int i = tid; i < 48*64; i += 128) {
        int o = i >> 6, c = i & 63;
        float wv = (o<8) ? qw[o*64+c] : (o<16) ? kw[(o-8)*64+c] : vw[(o-16)*64+c];
        swt[c*52 + o] = wv;
    }
    if (tid < 48) sbs[tid] = (tid<8)? qb[tid] : (tid<16? kb[tid-8] : vb[tid-16]);
    for (int i = tid; i < 64*32; i += 128) {
        int c = i >> 5, ce = i & 31;
        int pp_ = ce & 3, nn = ce >> 2;
        xsm[c*COLW + (8 + pp_*12 + nn)] = src[(long)nn*CIN*PP + (long)c*PP + pg + pp_];
    }
    __syncthreads();

    u64 acc[6];
    {
        const u64* bp = (const u64*)sbs;
        #pragma unroll
        for (int t=0;t<6;t++) acc[t] = bp[wq*6 + t];
    }
    #pragma unroll 8
    for (int c=0;c<64;c++) {
        float xv = xsm[c*COLW + col];
        u64 x2 = pack2(xv,xv);
        const ulonglong2* wr = (const ulonglong2*)(swt + c*52 + wq*12);
        ulonglong2 w0 = wr[0], w1 = wr[1], w2 = wr[2];
        acc[0]=fma2(x2,w0.x,acc[0]); acc[1]=fma2(x2,w0.y,acc[1]);
        acc[2]=fma2(x2,w1.x,acc[2]); acc[3]=fma2(x2,w1.y,acc[3]);
        acc[4]=fma2(x2,w2.x,acc[4]); acc[5]=fma2(x2,w2.y,acc[5]);
    }
    float o12[12];
    #pragma unroll
    for (int t=0;t<6;t++) unpack2(acc[t], o12[2*t], o12[2*t+1]);
    const int p = pg + pos;
    #pragma unroll
    for (int t=0;t<12;t++) {
        int o = wq*12 + t;
        if (o < 8)       g_q[(n*8  + o     )*PP + p] = o12[t];
        else if (o < 16) g_k[(n*8  + (o-8) )*PP + p] = o12[t];
        else             g_v[(n*32 + (o-16))*PP + p] = fmaxf(o12[t], 0.f);
    }
}

// ---------------------------------------------------------------------------
// Visual attention, split-K ([c2][j] layout — FROZEN), log2e-folded ex2.
// ---------------------------------------------------------------------------
__global__ __launch_bounds__(128) void vis_attn_split(void)
{
    __shared__ alignas(16) u64 ksu[4*128];    // [c2][j]
    __shared__ alignas(16) u64 vsu[16*128];   // [c2][j]
    const int tid = threadIdx.x;
    const int tile = blockIdx.x / NS, split = blockIdx.x % NS;
    const int n = tile / 6, tw = tile % 6;
    const int qp = tw*384 + tid;
    const float* qb_ = g_q + n*8*PP;
    const float* kb_ = g_k + n*8*PP;
    const float* vb_ = g_v + n*32*PP;
    const float L2E = 1.4426950408889634f;

    u64 qr[3][4];
    #pragma unroll
    for (int i=0;i<3;i++)
        #pragma unroll
        for (int r=0;r<4;r++)
            qr[i][r] = pack2(qb_[(2*r)*PP + qp + i*128]*L2E, qb_[(2*r+1)*PP + qp + i*128]*L2E);

    float l[3] = {0.f, 0.f, 0.f};
    u64 vacc[3][16];
    #pragma unroll
    for (int i=0;i<3;i++)
        #pragma unroll
        for (int t=0;t<16;t++) vacc[i][t] = 0ULL;

    const u64 z = 0ULL;
    for (int ch = split*2; ch < split*2 + 2; ch++) {
        __syncthreads();
        const int base = ch*128 + tid;
        #pragma unroll
        for (int r=0;r<4;r++)  ksu[r*128+tid] = pack2(kb_[(2*r)*PP+base], kb_[(2*r+1)*PP+base]);
        #pragma unroll
        for (int t=0;t<16;t++) vsu[t*128+tid] = pack2(vb_[(2*t)*PP+base], vb_[(2*t+1)*PP+base]);
        __syncthreads();
        #pragma unroll 2
        for (int j=0;j<128;j++) {
            u64 k0 = ksu[j], k1 = ksu[128+j], k2 = ksu[256+j], k3 = ksu[384+j];
            float pr[3];
            #pragma unroll
            for (int i=0;i<3;i++) {
                u64 d = add2(fma2(qr[i][0],k0,fma2(qr[i][1],k1,z)),
                             fma2(qr[i][2],k2,fma2(qr[i][3],k3,z)));
                float lo,hi; unpack2(d,lo,hi);
                pr[i] = ex2f(lo + hi);
                l[i] += pr[i];
            }
            u64 p0 = pack2(pr[0],pr[0]), p1 = pack2(pr[1],pr[1]), p2 = pack2(pr[2],pr[2]);
            #pragma unroll
            for (int t=0;t<16;t++) {
                u64 vr = vsu[t*128+j];
                vacc[0][t] = fma2(p0, vr, vacc[0][t]);
                vacc[1][t] = fma2(p1, vr, vacc[1][t]);
                vacc[2][t] = fma2(p2, vr, vacc[2][t]);
            }
        }
    }
    #pragma unroll
    for (int i=0;i<3;i++) {
        int q = n*PP + qp + i*128;
        g_pl[split*QTOT + q] = l[i];
        #pragma unroll
        for (int t=0;t<16;t++) {
            float lo,hi; unpack2(vacc[i][t], lo, hi);
            g_pv[(split*32 + 2*t  )*QTOT + q] = lo;
            g_pv[(split*32 + 2*t+1)*QTOT + q] = hi;
        }
    }
}

// ---------------------------------------------------------------------------
// Combine v4 (measured best — unchanged).
// ---------------------------------------------------------------------------
__global__ __launch_bounds__(256) void combine_kernel(
    const float* __restrict__ cw, const float* __restrict__ cb,
    float* __restrict__ out)
{
    __shared__ alignas(16) u64 cwt[32*16];    // [c][o2]
    __shared__ alignas(16) float cbs[32];
    __shared__ alignas(16) float avs[32*33];  // [cell][c], pitch 33
    const int tid = threadIdx.x;
    const int wq = tid >> 5, cell = tid & 31;

    for (int i = tid; i < 32*16; i += 256) {
        int c = i/16, t = i%16;
        cwt[i] = pack2(cw[(2*t)*32+c], cw[(2*t+1)*32+c]);
    }
    if (tid < 32) cbs[tid] = cb[tid];

    const int gid = blockIdx.x*32 + cell;
    const int n = gid/PP, p = gid%PP;

    float l = 0.f;
    #pragma unroll
    for (int sp=0; sp<NS; sp++) l += g_pl[sp*QTOT + gid];

    float va[4];
    #pragma unroll
    for (int j=0;j<4;j++) va[j] = 0.f;
    #pragma unroll
    for (int sp=0; sp<NS; sp++) {
        #pragma unroll
        for (int j=0;j<4;j++)
            va[j] += g_pv[(sp*32 + wq*4 + j)*QTOT + gid];
    }
    float inv = 1.f / l;
    #pragma unroll
    for (int j=0;j<4;j++) avs[cell*33 + wq*4 + j] = va[j] * inv;
    __syncthreads();

    u64 acc[2];
    {
        const u64* bp = (const u64*)cbs;
        acc[0] = bp[wq*2]; acc[1] = bp[wq*2+1];
    }
    #pragma unroll 8
    for (int c=0;c<32;c++) {
        float av = avs[cell*33 + c];
        u64 x2 = pack2(av, av);
        const ulonglong2* wr = (const ulonglong2*)(cwt + c*16 + wq*2);
        ulonglong2 w = wr[0];
        acc[0]=fma2(x2,w.x,acc[0]); acc[1]=fma2(x2,w.y,acc[1]);
    }
    float oc[4];
    unpack2(acc[0], oc[0], oc[1]);
    unpack2(acc[1], oc[2], oc[3]);

    float vv[4];
    #pragma unroll
    for (int j=0;j<4;j++) vv[j] = g_v[(n*32 + wq*4 + j)*PP + p];

    float* ob = out + (long)n*NSTRIDE + p;   // slice 0
    #pragma unroll
    for (int j=0;j<4;j++) {
        ob[(wq*4+j)*PP]      = oc[j];
        ob[(32+wq*4+j)*PP]   = vv[j];
    }

    float* xp = g_x + ((long)p*8 + n)*64;
    *(float4*)(xp + wq*4)      = make_float4(oc[0],oc[1],oc[2],oc[3]);
    *(float4*)(xp + 32 + wq*4) = make_float4(vv[0],vv[1],vv[2],vv[3]);
}

// ---------------------------------------------------------------------------
// MEGA temporal v6: 1 cell/thread, 32 cells/block, grid 576 (~4 blocks/SM).
// Same math/layout as v5 but single-cell (halved per-thread latency chain),
// smem ~32.5KB; weight fill stays the conflict-free linear g_wt copy.
// ex2.approx softmax (shift-invariant, guarded selects unchanged).
// ---------------------------------------------------------------------------
__global__ __launch_bounds__(128) void mega_temporal(
    const float* __restrict__ tq_b, const float* __restrict__ tk_b,
    const float* __restrict__ tv_b, const float* __restrict__ tc_b,
    float* __restrict__ out)
{
    __shared__ alignas(16) float swt[64*48];     // qkv weights [c][o]
    __shared__ alignas(16) float cwt[32*32];     // conv weights [c][o]
    __shared__ alignas(16) float sbs[48];
    __shared__ alignas(16) float cbs[32];
    __shared__ alignas(16) float xsm[32*68];     // head input [cell][c]
    __shared__ alignas(16) float qkvsm[34*52];   // rows 0,1 zero guards; row=2+cell

    const int tid  = threadIdx.x;
    const int wq   = tid >> 5, cell = tid & 31;
    const int pos  = cell >> 3, n = cell & 7;
    const int row  = 2 + cell;
    const int pg   = blockIdx.x*4;
    const float L2E = 1.4426950408889634f;

    for (int i = tid; i < 34*52; i += 128) qkvsm[i] = 0.f;

    {
        const float* gx = g_x + ((long)(pg+pos)*8 + n)*64 + wq*16;
        #pragma unroll
        for (int k=0;k<4;k++)
            *(float4*)(xsm + cell*68 + wq*16 + 4*k) = *(const float4*)(gx + 4*k);
    }

    for (int h=0; h<5; h++) {
        __syncthreads();   // barrier A: xsm writes done, prev weight reads done

        {
            const float4* wt4 = (const float4*)(g_wt + h*4096);
            float4* s4 = (float4*)swt;
            float4* c4p = (float4*)cwt;
            #pragma unroll
            for (int k=0;k<6;k++) s4[tid + 128*k] = wt4[tid + 128*k];
            #pragma unroll
            for (int k=0;k<2;k++) c4p[tid + 128*k] = wt4[768 + tid + 128*k];
        }
        if (tid < 48) sbs[tid] = (tid<8)? tq_b[h*8+tid] : (tid<16? tk_b[h*8+tid-8] : tv_b[h*32+tid-16]);
        if (tid < 32) cbs[tid] = tc_b[h*32+tid];
        __syncthreads();   // barrier B: weights ready

        // ---- phase 1: qkv 64->48, outputs [12wq,12wq+12) for own cell
        u64 acc[6];
        {
            const u64* bp = (const u64*)sbs;
            #pragma unroll
            for (int t=0;t<6;t++) acc[t] = bp[wq*6 + t];
        }
        #pragma unroll
        for (int c4=0; c4<64; c4+=4) {
            float4 xv = *(const float4*)(xsm + cell*68 + c4);
            float xs[4] = {xv.x, xv.y, xv.z, xv.w};
            #pragma unroll
            for (int j=0;j<4;j++) {
                u64 x2 = pack2(xs[j], xs[j]);
                const ulonglong2* wr = (const ulonglong2*)(swt + (c4+j)*48 + wq*12);
                ulonglong2 w0 = wr[0], w1 = wr[1], w2 = wr[2];
                acc[0]=fma2(x2,w0.x,acc[0]); acc[1]=fma2(x2,w0.y,acc[1]);
                acc[2]=fma2(x2,w1.x,acc[2]); acc[3]=fma2(x2,w1.y,acc[3]);
                acc[4]=fma2(x2,w2.x,acc[4]); acc[5]=fma2(x2,w2.y,acc[5]);
            }
        }
        {
            float o12[12];
            #pragma unroll
            for (int t=0;t<6;t++) unpack2(acc[t], o12[2*t], o12[2*t+1]);
            #pragma unroll
            for (int t=0;t<12;t++) if (12*wq + t >= 16) o12[t] = fmaxf(o12[t], 0.f);
            float* r = qkvsm + row*52 + wq*12;
            *(float4*)(r  ) = make_float4(o12[0],o12[1],o12[2],o12[3]);
            *(float4*)(r+4) = make_float4(o12[4],o12[5],o12[6],o12[7]);
            *(float4*)(r+8) = make_float4(o12[8],o12[9],o12[10],o12[11]);
        }
        __syncthreads();   // barrier C: qkv ready

        // ---- softmax (own cell; neighbor rows guarded by selects)
        float a0, a1, a2;
        {
            const float* rp = qkvsm + row*52;
            float4 q0=*(const float4*)(rp),     q1=*(const float4*)(rp+4);
            float4 k0a=*(const float4*)(rp+8),  k0b=*(const float4*)(rp+12);
            float4 k1a=*(const float4*)(rp+8-52),  k1b=*(const float4*)(rp+12-52);
            float4 k2a=*(const float4*)(rp+8-104), k2b=*(const float4*)(rp+12-104);
            float l2 = dot4(q0,k0a)+dot4(q1,k0b);
            float l1 = (n>=1) ? dot4(q0,k1a)+dot4(q1,k1b) : 0.f;
            float l0 = (n>=2) ? dot4(q0,k2a)+dot4(q1,k2b) : 0.f;
            float m  = fmaxf(l0, fmaxf(l1, l2));
            float e0=ex2f((l0-m)*L2E), e1=ex2f((l1-m)*L2E), e2=ex2f((l2-m)*L2E);
            float inv = 1.f/(e0+e1+e2);
            a2 = e2*inv;
            a1 = (n>=1) ? e1*inv : 0.f;
            a0 = (n>=2) ? e0*inv : 0.f;
        }

        // ---- fused attention-combine + out-conv, outputs [8wq,8wq+8)
        u64 ca[4];
        {
            const u64* bp = (const u64*)cbs;
            #pragma unroll
            for (int t=0;t<4;t++) ca[t] = bp[wq*4 + t];
        }
        #pragma unroll
        for (int c4=0; c4<32; c4+=4) {
            const float* vr = qkvsm + row*52 + 16 + c4;
            float4 v0=*(const float4*)(vr), v1=*(const float4*)(vr-52), v2=*(const float4*)(vr-104);
            float av[4];
            av[0]=a2*v0.x+a1*v1.x+a0*v2.x; av[1]=a2*v0.y+a1*v1.y+a0*v2.y;
            av[2]=a2*v0.z+a1*v1.z+a0*v2.z; av[3]=a2*v0.w+a1*v1.w+a0*v2.w;
            #pragma unroll
            for (int j=0;j<4;j++) {
                u64 x2 = pack2(av[j], av[j]);
                const ulonglong2* wr = (const ulonglong2*)(cwt + (c4+j)*32 + wq*8);
                ulonglong2 w0 = wr[0], w1 = wr[1];
                ca[0]=fma2(x2,w0.x,ca[0]); ca[1]=fma2(x2,w0.y,ca[1]);
                ca[2]=fma2(x2,w1.x,ca[2]); ca[3]=fma2(x2,w1.y,ca[3]);
            }
        }
        __syncthreads();   // all qkvsm reads done before next head's rewrite? (rewrite is next iter after barrier A;
                           // this barrier protects xsm rewrite below vs phase-1 xsm reads of other warps)
        {
            float oc[8];
            #pragma unroll
            for (int t=0;t<4;t++) unpack2(ca[t], oc[2*t], oc[2*t+1]);
            float4 va = *(const float4*)(qkvsm + row*52 + 16 + wq*8);
            float4 vb = *(const float4*)(qkvsm + row*52 + 16 + wq*8 + 4);
            float vq[8] = {va.x,va.y,va.z,va.w, vb.x,vb.y,vb.z,vb.w};

            float* ob = out + (long)n*NSTRIDE + (long)(h+1)*SLICE + pg + pos;
            #pragma unroll
            for (int j=0;j<8;j++) {
                ob[(8*wq+j)*PP]    = oc[j];
                ob[(32+8*wq+j)*PP] = vq[j];
            }
            float* xr = xsm + cell*68;
            *(float4*)(xr + 8*wq    ) = make_float4(oc[0],oc[1],oc[2],oc[3]);
            *(float4*)(xr + 8*wq + 4) = make_float4(oc[4],oc[5],oc[6],oc[7]);
            *(float4*)(xr + 32 + 8*wq    ) = va;
            *(float4*)(xr + 32 + 8*wq + 4) = vb;
        }
    }
}

// ---------------------------------------------------------------------------
extern "C" void kernel_launch(void* const* d_in, const int* in_sizes, int n_in,
                              void* d_out, int out_size)
{
    const float* x    = (const float*)d_in[0];
    const float* vq_w = (const float*)d_in[1];
    const float* vq_b = (const float*)d_in[2];
    const float* vk_w = (const float*)d_in[3];
    const float* vk_b = (const float*)d_in[4];
    const float* vv_w = (const float*)d_in[5];
    const float* vv_b = (const float*)d_in[6];
    const float* vc_w = (const float*)d_in[7];
    const float* vc_b = (const float*)d_in[8];
    const float* tq_w = (const float*)d_in[9];
    const float* tq_b = (const float*)d_in[10];
    const float* tk_w = (const float*)d_in[11];
    const float* tk_b = (const float*)d_in[12];
    const float* tv_w = (const float*)d_in[13];
    const float* tv_b = (const float*)d_in[14];
    const float* tc_w = (const float*)d_in[15];
    const float* tc_b = (const float*)d_in[16];
    float* out = (float*)d_out;

    transpose_w<<<80,256>>>(tq_w, tk_w, tv_w, tc_w);
    qkv0_kernel<<<576,128>>>(x, vq_w, vq_b, vk_w, vk_b, vv_w, vv_b);
    vis_attn_split<<<48*NS,128>>>();
    combine_kernel<<<576,256>>>(vc_w, vc_b, out);
    mega_temporal<<<576,128>>>(tq_b, tk_b, tv_b, tc_b, out);
}